// round 1
// baseline (speedup 1.0000x reference)
#include <cuda_runtime.h>

#define TPB 256
#define MAXB 128
#define MAXP 32768
#define MAXO 32
#define TIECAP 512

// ---------------- scratch (__device__ globals; zero-init at load) ----------
__device__ float              g_best_ov [(size_t)MAXB * MAXP];
__device__ unsigned char      g_best_ti [(size_t)MAXB * MAXP];
__device__ float              g_loss_cpp[(size_t)MAXB * MAXP];
__device__ unsigned char      g_conf    [(size_t)MAXB * MAXP];
__device__ unsigned int       g_hist    [(size_t)MAXB * 65536];   // self-cleaning
__device__ unsigned long long g_best_prior[MAXB * MAXO];
__device__ int                g_numpos [MAXB];
__device__ int                g_bin1   [MAXB];
__device__ int                g_k2     [MAXB];
__device__ unsigned int       g_T      [MAXB];
__device__ int                g_needeq [MAXB];
__device__ int                g_tiecnt [MAXB];
__device__ int                g_tiebuf [MAXB * TIECAP];
__device__ double             g_accB   [MAXB][3];   // loss_l, loss_c, loss_r

// ---------------- helpers ---------------------------------------------------
__device__ __forceinline__ float sl1(float d) {
    d = fabsf(d);
    return d < 1.0f ? 0.5f * d * d : d - 0.5f;
}

__device__ __forceinline__ float bce_term(float x, float tgt) {
    return fmaxf(x, 0.0f) - x * tgt + log1pf(expf(-fabsf(x)));
}

__device__ __forceinline__ float bce4(const float x[4], int cls) {
    float s = 0.0f;
#pragma unroll
    for (int c = 0; c < 4; c++)
        s += bce_term(x[c], (c == cls) ? 0.925f : 0.025f);  // ALPHA=0.1
    return s;
}

// block sum over 256 threads; result valid on thread 0
__device__ __forceinline__ float blocksum(float v, float* sh) {
    int tid = threadIdx.x;
#pragma unroll
    for (int s = 16; s; s >>= 1) v += __shfl_down_sync(0xFFFFFFFFu, v, s);
    if ((tid & 31) == 0) sh[tid >> 5] = v;
    __syncthreads();
    if (tid < 8) {
        v = sh[tid];
#pragma unroll
        for (int s = 4; s; s >>= 1) v += __shfl_down_sync(0xFFu, v, s);
    }
    __syncthreads();   // safe reuse of sh by a following call
    return v;
}

// ---------------- kernel A: match -------------------------------------------
__global__ void kmatch(const float* __restrict__ targets,
                       const float* __restrict__ priors, int P, int O) {
    int b = blockIdx.y;
    int p = blockIdx.x * TPB + threadIdx.x;
    __shared__ float s_t[MAXO * 6];
    __shared__ unsigned long long s_red[8];

    for (int i = threadIdx.x; i < O * 6; i += TPB)
        s_t[i] = targets[(size_t)b * O * 6 + i];
    __syncthreads();

    bool valid = (p < P);
    float px0 = 0, py0 = 0, px1 = 0, py1 = 0, areaB = 0;
    if (valid) {
        float cx = priors[p * 4 + 0], cy = priors[p * 4 + 1];
        float w  = priors[p * 4 + 2], h  = priors[p * 4 + 3];
        px0 = cx - w * 0.5f; py0 = cy - h * 0.5f;
        px1 = cx + w * 0.5f; py1 = cy + h * 0.5f;
        areaB = (px1 - px0) * (py1 - py0);
    }

    float bestv = -1.0f;
    int   besto = 0;

    for (int o = 0; o < O; o++) {
        float iou = 0.0f;
        if (valid) {
            float tx0 = s_t[o * 6 + 0], ty0 = s_t[o * 6 + 1];
            float tx1 = s_t[o * 6 + 2], ty1 = s_t[o * 6 + 3];
            float ix = fmaxf(fminf(tx1, px1) - fmaxf(tx0, px0), 0.0f);
            float iy = fmaxf(fminf(ty1, py1) - fmaxf(ty0, py0), 0.0f);
            float inter = ix * iy;
            float areaA = (tx1 - tx0) * (ty1 - ty0);
            iou = inter / (areaA + areaB - inter);
            if (iou > bestv) { bestv = iou; besto = o; }   // first-max (jnp.argmax axis=0)
        }
        // block argmax over p; tie -> smaller p (jnp.argmax axis=1 first-occurrence)
        unsigned long long pk = valid
            ? ((((unsigned long long)__float_as_uint(iou)) << 32) | (unsigned)(~p))
            : 0ull;
#pragma unroll
        for (int s = 16; s; s >>= 1) {
            unsigned long long o2 = __shfl_down_sync(0xFFFFFFFFu, pk, s);
            if (o2 > pk) pk = o2;
        }
        if ((threadIdx.x & 31) == 0) s_red[threadIdx.x >> 5] = pk;
        __syncthreads();
        if (threadIdx.x < 8) {
            pk = s_red[threadIdx.x];
#pragma unroll
            for (int s = 4; s; s >>= 1) {
                unsigned long long o2 = __shfl_down_sync(0xFFu, pk, s);
                if (o2 > pk) pk = o2;
            }
            if (threadIdx.x == 0) atomicMax(&g_best_prior[b * O + o], pk);
        }
        __syncthreads();
    }

    if (valid) {
        size_t idx = (size_t)b * P + p;
        g_best_ov[idx] = bestv;
        g_best_ti[idx] = (unsigned char)besto;
    }
}

// ---------------- kernel B: forced matches (last o wins) --------------------
__global__ void kforce(int B, int P, int O) {
    int b = blockIdx.x * blockDim.x + threadIdx.x;
    if (b >= B) return;
    for (int o = 0; o < O; o++) {
        unsigned long long pk = g_best_prior[b * O + o];
        unsigned p = ~(unsigned)pk;
        size_t idx = (size_t)b * P + p;
        g_best_ov[idx] = 2.0f;
        g_best_ti[idx] = (unsigned char)o;
    }
}

// ---------------- kernel C: per-prior losses + loss_cpp ---------------------
__global__ void kloss(const float* __restrict__ loc, const float* __restrict__ cnf,
                      const float* __restrict__ reg, const float* __restrict__ targets,
                      const float* __restrict__ priors, int P, int O) {
    int b = blockIdx.y;
    int p = blockIdx.x * TPB + threadIdx.x;
    __shared__ float s_t[MAXO * 6];
    __shared__ float sh[8];
    for (int i = threadIdx.x; i < O * 6; i += TPB)
        s_t[i] = targets[(size_t)b * O * 6 + i];
    __syncthreads();

    float ll = 0, lc = 0, lr = 0;
    bool pos = false;
    if (p < P) {
        size_t idx = (size_t)b * P + p;
        float ov = g_best_ov[idx];
        int   ti = g_best_ti[idx];
        int conf = (ov < 0.5f) ? 0 : (int)s_t[ti * 6 + 4];
        g_conf[idx] = (unsigned char)conf;
        float x[4];
#pragma unroll
        for (int c = 0; c < 4; c++) x[c] = cnf[idx * 4 + c];
        if (conf > 0) {
            pos = true;
            float cx = priors[p * 4 + 0], cy = priors[p * 4 + 1];
            float w  = priors[p * 4 + 2], h  = priors[p * 4 + 3];
            float mx = (s_t[ti * 6 + 0] + s_t[ti * 6 + 2]) * 0.5f;
            float my = (s_t[ti * 6 + 1] + s_t[ti * 6 + 3]) * 0.5f;
            float lt0 = (mx - cx) / (0.1f * w);
            float lt1 = (my - cy) / (0.1f * h);
            ll = sl1(loc[idx * 2 + 0] - lt0) + sl1(loc[idx * 2 + 1] - lt1);
            lr = sl1(reg[idx] - s_t[ti * 6 + 5]);
            lc = bce4(x, conf);
            g_loss_cpp[idx] = 0.0f;
        } else {
            float m = fmaxf(fmaxf(x[0], x[1]), fmaxf(x[2], x[3]));
            float s = expf(x[0] - m) + expf(x[1] - m) + expf(x[2] - m) + expf(x[3] - m);
            g_loss_cpp[idx] = m + logf(s) - x[0];   // lse - picked (cnf_t==0)
        }
    }
    int np = __syncthreads_count(pos);
    float tll = blocksum(ll, sh);
    float tlc = blocksum(lc, sh);
    float tlr = blocksum(lr, sh);
    if (threadIdx.x == 0) {
        if (np) atomicAdd(&g_numpos[b], np);
        atomicAdd(&g_accB[b][0], (double)tll);
        atomicAdd(&g_accB[b][1], (double)tlc);
        atomicAdd(&g_accB[b][2], (double)tlr);
    }
}

// ---------------- radix-select pass 1/2 histograms --------------------------
__global__ void khist1(int P) {
    int b = blockIdx.y;
    int p = blockIdx.x * TPB + threadIdx.x;
    if (p >= P) return;
    unsigned bits = __float_as_uint(g_loss_cpp[(size_t)b * P + p]);
    atomicAdd(&g_hist[(size_t)b * 65536 + (bits >> 16)], 1u);
}

__global__ void khist2(int P) {
    int b = blockIdx.y;
    int p = blockIdx.x * TPB + threadIdx.x;
    if (p >= P) return;
    unsigned bits = __float_as_uint(g_loss_cpp[(size_t)b * P + p]);
    if ((int)(bits >> 16) == g_bin1[b])
        atomicAdd(&g_hist[(size_t)b * 65536 + (bits & 0xFFFFu)], 1u);
}

// find k-th largest bin from the top; self-zero the histogram afterwards
__global__ void kscan(int P, int pass) {
    int b = blockIdx.x;
    unsigned* h = &g_hist[(size_t)b * 65536];
    __shared__ unsigned s_ch[1024];
    __shared__ unsigned s_suf[1024];
    int t = threadIdx.x;
    int base = t * 64;
    unsigned cs = 0;
#pragma unroll
    for (int i = 0; i < 64; i++) cs += h[base + i];
    s_ch[t] = cs;
    __syncthreads();
    if (t == 0) {
        unsigned run = 0;
        for (int u = 1023; u >= 0; u--) { s_suf[u] = run; run += s_ch[u]; }
    }
    __syncthreads();
    int k = (pass == 0) ? min(3 * g_numpos[b], P - 1) : g_k2[b];
    if (s_suf[t] < (unsigned)k && s_suf[t] + s_ch[t] >= (unsigned)k) {
        unsigned krem = (unsigned)k - s_suf[t];
        unsigned cum = 0;
        for (int bin = base + 63; bin >= base; bin--) {
            unsigned c = h[bin];
            cum += c;
            if (cum >= krem) {
                if (pass == 0) {
                    g_bin1[b] = bin;
                    g_k2[b]   = (int)(krem - (cum - c));
                } else {
                    g_T[b]      = (((unsigned)g_bin1[b]) << 16) | (unsigned)bin;
                    g_needeq[b] = (int)(krem - (cum - c));
                }
                break;
            }
        }
    }
    __syncthreads();
#pragma unroll
    for (int i = 0; i < 64; i++) h[base + i] = 0;   // ready for next pass/launch
}

// ---------------- kernel D: hard-negative BCE -------------------------------
__global__ void kneg(const float* __restrict__ cnf, int P) {
    int b = blockIdx.y;
    int p = blockIdx.x * TPB + threadIdx.x;
    __shared__ float sh[8];
    float lc = 0.0f;
    if (p < P) {
        size_t idx = (size_t)b * P + p;
        if (g_conf[idx] == 0) {
            unsigned bits = __float_as_uint(g_loss_cpp[idx]);
            unsigned T = g_T[b];
            if (bits > T) {
                float x[4];
#pragma unroll
                for (int c = 0; c < 4; c++) x[c] = cnf[idx * 4 + c];
                lc = bce4(x, 0);
            } else if (bits == T) {
                int t = atomicAdd(&g_tiecnt[b], 1);
                if (t < TIECAP) g_tiebuf[b * TIECAP + t] = p;
            }
        }
    }
    float tot = blocksum(lc, sh);
    if (threadIdx.x == 0 && tot != 0.0f)
        atomicAdd(&g_accB[b][1], (double)tot);
}

// ---------------- kernel E: ties at exact threshold (smallest indices win) --
__global__ void ktie(const float* __restrict__ cnf, int P) {
    int b = blockIdx.x;
    int t = min(g_tiecnt[b], TIECAP);
    int need = g_needeq[b];
    __shared__ float sh[8];
    float lc = 0.0f;
    for (int i = threadIdx.x; i < t; i += TPB) {
        int p = g_tiebuf[b * TIECAP + i];
        int rank = 0;
        for (int j = 0; j < t; j++) rank += (g_tiebuf[b * TIECAP + j] < p);
        if (rank < need) {
            float x[4];
            size_t idx = (size_t)b * P + p;
#pragma unroll
            for (int c = 0; c < 4; c++) x[c] = cnf[idx * 4 + c];
            lc += bce4(x, 0);
        }
    }
    float tot = blocksum(lc, sh);
    if (threadIdx.x == 0 && tot != 0.0f)
        atomicAdd(&g_accB[b][1], (double)tot);
}

// ---------------- final reduce ----------------------------------------------
__global__ void kfinal(float* __restrict__ out, int B) {
    if (threadIdx.x == 0) {
        double N = 0, l0 = 0, l1 = 0, l2 = 0;
        for (int b = 0; b < B; b++) {
            N  += (double)g_numpos[b];
            l0 += g_accB[b][0];
            l1 += g_accB[b][1];
            l2 += g_accB[b][2];
        }
        out[0] = (float)(l0 / N);
        out[1] = (float)(l1 / N);
        out[2] = (float)(l2 / N);
    }
}

// ---------------- launch ------------------------------------------------------
extern "C" void kernel_launch(void* const* d_in, const int* in_sizes, int n_in,
                              void* d_out, int out_size) {
    const float* loc     = (const float*)d_in[0];
    const float* cnf     = (const float*)d_in[1];
    const float* reg     = (const float*)d_in[2];
    const float* targets = (const float*)d_in[3];
    const float* priors  = (const float*)d_in[4];

    int P = in_sizes[4] / 4;
    int B = in_sizes[0] / (2 * P);
    int O = in_sizes[3] / (6 * B);

    void *pbp, *pnp, *ptc, *pacc;
    cudaGetSymbolAddress(&pbp,  g_best_prior);
    cudaGetSymbolAddress(&pnp,  g_numpos);
    cudaGetSymbolAddress(&ptc,  g_tiecnt);
    cudaGetSymbolAddress(&pacc, g_accB);
    cudaMemsetAsync(pbp,  0, sizeof(unsigned long long) * B * O, 0);
    cudaMemsetAsync(pnp,  0, sizeof(int) * B, 0);
    cudaMemsetAsync(ptc,  0, sizeof(int) * B, 0);
    cudaMemsetAsync(pacc, 0, sizeof(double) * 3 * B, 0);

    dim3 grid((P + TPB - 1) / TPB, B);
    kmatch <<<grid, TPB>>>(targets, priors, P, O);
    kforce <<<1, 128>>>(B, P, O);
    kloss  <<<grid, TPB>>>(loc, cnf, reg, targets, priors, P, O);
    khist1 <<<grid, TPB>>>(P);
    kscan  <<<B, 1024>>>(P, 0);
    khist2 <<<grid, TPB>>>(P);
    kscan  <<<B, 1024>>>(P, 1);
    kneg   <<<grid, TPB>>>(cnf, P);
    ktie   <<<B, TPB>>>(cnf, P);
    kfinal <<<1, 32>>>((float*)d_out, B);
}

// round 2
// speedup vs baseline: 2.8951x; 2.8951x over previous
#include <cuda_runtime.h>

#define TPB   256      // threads for kmatch / kneg
#define LTPB  512      // threads for kloss / khist2 / khist3
#define SLC   4        // slices per batch for per-batch-owned histograms
#define MAXB  128
#define MAXP  32768
#define MAXO  32
#define TIECAP 1024

// ---------------- scratch (__device__ globals) ------------------------------
__device__ unsigned char      g_match   [(size_t)MAXB * MAXP];  // bit7=matched, low=ti
__device__ float              g_loss_cpp[(size_t)MAXB * MAXP];
__device__ unsigned int       g_hist    [(size_t)MAXB * SLC * 2048];
__device__ unsigned long long g_best_prior[MAXB * MAXO];
__device__ int                g_numpos [MAXB];
__device__ int                g_bin_a  [MAXB];
__device__ int                g_bin_b  [MAXB];
__device__ int                g_kcur   [MAXB];
__device__ unsigned int       g_T      [MAXB];
__device__ int                g_needeq [MAXB];
__device__ int                g_tiecnt [MAXB];
__device__ int                g_tiebuf [MAXB * TIECAP];
__device__ double             g_accB   [MAXB][3];

// ---------------- helpers ---------------------------------------------------
__device__ __forceinline__ float sl1(float d) {
    d = fabsf(d);
    return d < 1.0f ? 0.5f * d * d : d - 0.5f;
}
__device__ __forceinline__ float bce_term(float x, float tgt) {
    return fmaxf(x, 0.0f) - x * tgt + log1pf(expf(-fabsf(x)));
}
__device__ __forceinline__ float bce4v(float x0, float x1, float x2, float x3, int cls) {
    float s = 0.0f;
    s += bce_term(x0, (0 == cls) ? 0.925f : 0.025f);
    s += bce_term(x1, (1 == cls) ? 0.925f : 0.025f);
    s += bce_term(x2, (2 == cls) ? 0.925f : 0.025f);
    s += bce_term(x3, (3 == cls) ? 0.925f : 0.025f);
    return s;
}

// block sum; works for 256 or 512 threads; result valid on thread 0
template <int NT>
__device__ __forceinline__ float blocksumT(float v, float* sh) {
    int tid = threadIdx.x;
#pragma unroll
    for (int s = 16; s; s >>= 1) v += __shfl_down_sync(0xFFFFFFFFu, v, s);
    if ((tid & 31) == 0) sh[tid >> 5] = v;
    __syncthreads();
    const int NW = NT / 32;
    if (tid < NW) {
        v = sh[tid];
#pragma unroll
        for (int s = NW / 2; s; s >>= 1) v += __shfl_down_sync((1u << NW) - 1u, v, s);
    }
    __syncthreads();
    return v;
}

// ---------------- kernel A: match -------------------------------------------
// 2 priors per thread; smem atomicMax replaces per-o block reductions.
__global__ void kmatch(const float* __restrict__ targets,
                       const float4* __restrict__ priors4, int P, int O) {
    int b = blockIdx.y;
    __shared__ float s_t[MAXO * 5];              // x0,y0,x1,y1,areaA
    __shared__ unsigned long long s_best[MAXO];
    int tid = threadIdx.x;
    if (tid < O) {
        const float* tr = targets + ((size_t)b * O + tid) * 6;
        float x0 = tr[0], y0 = tr[1], x1 = tr[2], y1 = tr[3];
        s_t[tid * 5 + 0] = x0; s_t[tid * 5 + 1] = y0;
        s_t[tid * 5 + 2] = x1; s_t[tid * 5 + 3] = y1;
        s_t[tid * 5 + 4] = (x1 - x0) * (y1 - y0);
        s_best[tid] = 0ull;
    }
    __syncthreads();

    int p0 = blockIdx.x * (TPB * 2) + tid;
    int p1 = p0 + TPB;
    bool v0 = p0 < P, v1 = p1 < P;
    float4 pa = priors4[v0 ? p0 : 0];
    float4 pb = priors4[v1 ? p1 : 0];
    float ax0 = pa.x - pa.z * 0.5f, ay0 = pa.y - pa.w * 0.5f;
    float ax1 = pa.x + pa.z * 0.5f, ay1 = pa.y + pa.w * 0.5f;
    float aA = (ax1 - ax0) * (ay1 - ay0);
    float bx0 = pb.x - pb.z * 0.5f, by0 = pb.y - pb.w * 0.5f;
    float bx1 = pb.x + pb.z * 0.5f, by1 = pb.y + pb.w * 0.5f;
    float aB = (bx1 - bx0) * (by1 - by0);

    float bv0 = -1.0f, bv1 = -1.0f;
    int bo0 = 0, bo1 = 0;

    for (int o = 0; o < O; o++) {
        float tx0 = s_t[o * 5 + 0], ty0 = s_t[o * 5 + 1];
        float tx1 = s_t[o * 5 + 2], ty1 = s_t[o * 5 + 3];
        float tA  = s_t[o * 5 + 4];

        float ix = fmaxf(fminf(tx1, ax1) - fmaxf(tx0, ax0), 0.0f);
        float iy = fmaxf(fminf(ty1, ay1) - fmaxf(ty0, ay0), 0.0f);
        float in0 = ix * iy;
        float iou0 = 0.0f;
        if (in0 > 0.0f) iou0 = in0 / (tA + aA - in0);

        float jx = fmaxf(fminf(tx1, bx1) - fmaxf(tx0, bx0), 0.0f);
        float jy = fmaxf(fminf(ty1, by1) - fmaxf(ty0, by0), 0.0f);
        float in1 = jx * jy;
        float iou1 = 0.0f;
        if (in1 > 0.0f) iou1 = in1 / (tA + aB - in1);

        if (iou0 > bv0) { bv0 = iou0; bo0 = o; }
        if (iou1 > bv1) { bv1 = iou1; bo1 = o; }

        if (v0 && iou0 > 0.0f)
            atomicMax(&s_best[o],
                (((unsigned long long)__float_as_uint(iou0)) << 32) | (unsigned)(~p0));
        if (v1 && iou1 > 0.0f)
            atomicMax(&s_best[o],
                (((unsigned long long)__float_as_uint(iou1)) << 32) | (unsigned)(~p1));
    }

    if (v0) g_match[(size_t)b * P + p0] =
        (unsigned char)(bo0 | (bv0 >= 0.5f ? 0x80 : 0));
    if (v1) g_match[(size_t)b * P + p1] =
        (unsigned char)(bo1 | (bv1 >= 0.5f ? 0x80 : 0));

    __syncthreads();
    if (tid < O) atomicMax(&g_best_prior[b * O + tid], s_best[tid]);
}

// ---------------- kernel B: per-prior losses + loss_cpp + hist pass 1 -------
// grid (SLC, B); each block owns one slice of one batch exclusively.
__global__ void kloss(const float2* __restrict__ loc2, const float4* __restrict__ cnf4,
                      const float* __restrict__ reg, const float* __restrict__ targets,
                      const float4* __restrict__ priors4, int P, int O) {
    int b = blockIdx.y, slc = blockIdx.x;
    int cnt0 = (P + SLC - 1) / SLC;
    int base = slc * cnt0;
    int cnt = min(P - base, cnt0);

    __shared__ float s_t[MAXO * 6];
    __shared__ unsigned s_hist[2048];
    __shared__ unsigned char s_over[8192];
    __shared__ float sh[LTPB / 32];

    int tid = threadIdx.x;
    for (int i = tid; i < O * 6; i += LTPB) s_t[i] = targets[(size_t)b * O * 6 + i];
    for (int i = tid; i < 2048; i += LTPB) s_hist[i] = 0;
    for (int i = tid; i < 8192 / 4; i += LTPB) ((unsigned*)s_over)[i] = 0xFFFFFFFFu;
    __syncthreads();
    if (tid == 0) {  // forced matches (ascending o => last wins)
        for (int o = 0; o < O; o++) {
            unsigned p = ~(unsigned)g_best_prior[b * O + o];
            if ((int)p >= base && (int)p < base + cnt) s_over[p - base] = (unsigned char)o;
        }
    }
    __syncthreads();

    float ll = 0, lc = 0, lr = 0, np = 0;
    for (int i = tid; i < cnt; i += LTPB) {
        int p = base + i;
        size_t idx = (size_t)b * P + p;
        unsigned char mv = g_match[idx];
        unsigned char ov = s_over[i];
        int ti; bool matched;
        if (ov != 0xFF) { ti = ov; matched = true; }
        else            { ti = mv & 0x7F; matched = (mv >> 7) != 0; }

        float4 x = cnf4[idx];
        float lcpp;
        int conf = matched ? (int)s_t[ti * 6 + 4] : 0;
        if (conf > 0) {
            np += 1.0f;
            float4 pr = priors4[p];
            float mx = (s_t[ti * 6 + 0] + s_t[ti * 6 + 2]) * 0.5f;
            float my = (s_t[ti * 6 + 1] + s_t[ti * 6 + 3]) * 0.5f;
            float lt0 = (mx - pr.x) / (0.1f * pr.z);
            float lt1 = (my - pr.y) / (0.1f * pr.w);
            float2 lv = loc2[idx];
            ll += sl1(lv.x - lt0) + sl1(lv.y - lt1);
            lr += sl1(reg[idx] - s_t[ti * 6 + 5]);
            lc += bce4v(x.x, x.y, x.z, x.w, conf);
            lcpp = 0.0f;
        } else {
            float m = fmaxf(fmaxf(x.x, x.y), fmaxf(x.z, x.w));
            float s = expf(x.x - m) + expf(x.y - m) + expf(x.z - m) + expf(x.w - m);
            lcpp = m + logf(s) - x.x;
        }
        g_loss_cpp[idx] = lcpp;
        atomicAdd(&s_hist[__float_as_uint(lcpp) >> 21], 1u);
    }
    __syncthreads();

    unsigned* gh = &g_hist[((size_t)b * SLC + slc) * 2048];
    for (int i = tid; i < 2048; i += LTPB) gh[i] = s_hist[i];

    float tll = blocksumT<LTPB>(ll, sh);
    float tlc = blocksumT<LTPB>(lc, sh);
    float tlr = blocksumT<LTPB>(lr, sh);
    float tnp = blocksumT<LTPB>(np, sh);
    if (tid == 0) {
        atomicAdd(&g_accB[b][0], (double)tll);
        atomicAdd(&g_accB[b][1], (double)tlc);
        atomicAdd(&g_accB[b][2], (double)tlr);
        atomicAdd(&g_numpos[b], (int)tnp);
    }
}

// ---------------- radix pass 2/3 histograms (smem, exclusive global write) --
__global__ void khist2(int P) {
    int b = blockIdx.y, slc = blockIdx.x;
    int cnt0 = (P + SLC - 1) / SLC;
    int base = slc * cnt0;
    int cnt = min(P - base, cnt0);
    __shared__ unsigned s_hist[2048];
    int tid = threadIdx.x;
    int ba = g_bin_a[b];
    for (int i = tid; i < 2048; i += LTPB) s_hist[i] = 0;
    __syncthreads();
    for (int i = tid; i < cnt; i += LTPB) {
        unsigned bits = __float_as_uint(g_loss_cpp[(size_t)b * P + base + i]);
        if ((int)(bits >> 21) == ba)
            atomicAdd(&s_hist[(bits >> 10) & 0x7FF], 1u);
    }
    __syncthreads();
    unsigned* gh = &g_hist[((size_t)b * SLC + slc) * 2048];
    for (int i = tid; i < 2048; i += LTPB) gh[i] = s_hist[i];
}

__global__ void khist3(int P) {
    int b = blockIdx.y, slc = blockIdx.x;
    int cnt0 = (P + SLC - 1) / SLC;
    int base = slc * cnt0;
    int cnt = min(P - base, cnt0);
    __shared__ unsigned s_hist[1024];
    int tid = threadIdx.x;
    int top22 = (g_bin_a[b] << 11) | g_bin_b[b];   // negative if invalid
    for (int i = tid; i < 1024; i += LTPB) s_hist[i] = 0;
    __syncthreads();
    for (int i = tid; i < cnt; i += LTPB) {
        unsigned bits = __float_as_uint(g_loss_cpp[(size_t)b * P + base + i]);
        if ((int)(bits >> 10) == top22)
            atomicAdd(&s_hist[bits & 0x3FF], 1u);
    }
    __syncthreads();
    unsigned* gh = &g_hist[((size_t)b * SLC + slc) * 2048];
    for (int i = tid; i < 1024; i += LTPB) gh[i] = s_hist[i];
}

// ---------------- scan: find k-th largest bin (suffix walk from top) --------
__global__ void kscan(int P, int level, int NB) {
    int b = blockIdx.x, t = threadIdx.x;
    __shared__ unsigned s_h[2048];
    __shared__ unsigned s_ce[256];
    int CH = NB / 256;
    const unsigned* gh = &g_hist[(size_t)b * SLC * 2048];
    for (int j = t; j < NB; j += 256) {
        unsigned s = 0;
#pragma unroll
        for (int s2 = 0; s2 < SLC; s2++) s += gh[s2 * 2048 + j];
        s_h[j] = s;
    }
    __syncthreads();
    unsigned cs = 0;
    for (int c = 0; c < CH; c++) cs += s_h[t * CH + c];
    s_ce[t] = cs;
    __syncthreads();
    if (t == 0) {
        unsigned run = 0;
        for (int u = 255; u >= 0; u--) { unsigned v = s_ce[u]; s_ce[u] = run; run += v; }
    }
    __syncthreads();

    int k;
    if (level == 0) { int npv = g_numpos[b]; k = min(3 * npv, P - 1); }
    else            k = g_kcur[b];

    if (k > 0) {
        unsigned excl = s_ce[t];
        for (int j = (t + 1) * CH - 1; j >= t * CH; j--) {
            unsigned h = s_h[j];
            if (excl < (unsigned)k && excl + h >= (unsigned)k) {
                unsigned krem = (unsigned)k - excl;
                if (level == 0)      { g_bin_a[b] = j; g_kcur[b] = (int)krem; }
                else if (level == 1) { g_bin_b[b] = j; g_kcur[b] = (int)krem; }
                else {
                    g_T[b] = (((unsigned)g_bin_a[b]) << 21) |
                             (((unsigned)g_bin_b[b]) << 10) | (unsigned)j;
                    g_needeq[b] = (int)krem;
                }
                break;
            }
            excl += h;
        }
    } else if (t == 0) {
        if (level == 0)      { g_bin_a[b] = -1; g_kcur[b] = 0; }
        else if (level == 1) { g_bin_b[b] = -1; g_kcur[b] = 0; }
        else                 { g_T[b] = 0xFFFFFFFFu; g_needeq[b] = 0; }
    }
}

// ---------------- kernel D: hard-negative BCE -------------------------------
__global__ void kneg(const float4* __restrict__ cnf4, int P) {
    int b = blockIdx.y;
    int p = blockIdx.x * TPB + threadIdx.x;
    __shared__ float sh[TPB / 32];
    float lc = 0.0f;
    if (p < P) {
        size_t idx = (size_t)b * P + p;
        unsigned bits = __float_as_uint(g_loss_cpp[idx]);
        unsigned T = g_T[b];
        if (bits > T) {
            float4 x = cnf4[idx];
            lc = bce4v(x.x, x.y, x.z, x.w, 0);
        } else if (bits == T && T != 0u) {
            int t = atomicAdd(&g_tiecnt[b], 1);
            if (t < TIECAP) g_tiebuf[b * TIECAP + t] = p;
        }
    }
    float tot = blocksumT<TPB>(lc, sh);
    if (threadIdx.x == 0 && tot != 0.0f)
        atomicAdd(&g_accB[b][1], (double)tot);
}

// ---------------- kernel E: ties at threshold (smallest indices win) --------
__global__ void ktie(const float4* __restrict__ cnf4, int P) {
    int b = blockIdx.x;
    int t = min(g_tiecnt[b], TIECAP);
    int need = g_needeq[b];
    __shared__ float sh[TPB / 32];
    float lc = 0.0f;
    for (int i = threadIdx.x; i < t; i += TPB) {
        int p = g_tiebuf[b * TIECAP + i];
        int rank = 0;
        for (int j = 0; j < t; j++) rank += (g_tiebuf[b * TIECAP + j] < p);
        if (rank < need) {
            float4 x = cnf4[(size_t)b * P + p];
            lc += bce4v(x.x, x.y, x.z, x.w, 0);
        }
    }
    float tot = blocksumT<TPB>(lc, sh);
    if (threadIdx.x == 0 && tot != 0.0f)
        atomicAdd(&g_accB[b][1], (double)tot);
}

// ---------------- final reduce ----------------------------------------------
__global__ void kfinal(float* __restrict__ out, int B) {
    if (threadIdx.x == 0) {
        double N = 0, l0 = 0, l1 = 0, l2 = 0;
        for (int b = 0; b < B; b++) {
            N  += (double)g_numpos[b];
            l0 += g_accB[b][0];
            l1 += g_accB[b][1];
            l2 += g_accB[b][2];
        }
        out[0] = (float)(l0 / N);
        out[1] = (float)(l1 / N);
        out[2] = (float)(l2 / N);
    }
}

// ---------------- launch ------------------------------------------------------
extern "C" void kernel_launch(void* const* d_in, const int* in_sizes, int n_in,
                              void* d_out, int out_size) {
    const float* loc     = (const float*)d_in[0];
    const float* cnf     = (const float*)d_in[1];
    const float* reg     = (const float*)d_in[2];
    const float* targets = (const float*)d_in[3];
    const float* priors  = (const float*)d_in[4];

    int P = in_sizes[4] / 4;
    int B = in_sizes[0] / (2 * P);
    int O = in_sizes[3] / (6 * B);

    void *pbp, *pnp, *ptc, *pacc;
    cudaGetSymbolAddress(&pbp,  g_best_prior);
    cudaGetSymbolAddress(&pnp,  g_numpos);
    cudaGetSymbolAddress(&ptc,  g_tiecnt);
    cudaGetSymbolAddress(&pacc, g_accB);
    cudaMemsetAsync(pbp,  0, sizeof(unsigned long long) * B * O, 0);
    cudaMemsetAsync(pnp,  0, sizeof(int) * B, 0);
    cudaMemsetAsync(ptc,  0, sizeof(int) * B, 0);
    cudaMemsetAsync(pacc, 0, sizeof(double) * 3 * B, 0);

    dim3 gmatch((P + 2 * TPB - 1) / (2 * TPB), B);
    dim3 gslice(SLC, B);
    dim3 gflat((P + TPB - 1) / TPB, B);

    kmatch <<<gmatch, TPB>>>(targets, (const float4*)priors, P, O);
    kloss  <<<gslice, LTPB>>>((const float2*)loc, (const float4*)cnf, reg,
                              targets, (const float4*)priors, P, O);
    kscan  <<<B, 256>>>(P, 0, 2048);
    khist2 <<<gslice, LTPB>>>(P);
    kscan  <<<B, 256>>>(P, 1, 2048);
    khist3 <<<gslice, LTPB>>>(P);
    kscan  <<<B, 256>>>(P, 2, 1024);
    kneg   <<<gflat, TPB>>>((const float4*)cnf, P);
    ktie   <<<B, TPB>>>((const float4*)cnf, P);
    kfinal <<<1, 32>>>((float*)d_out, B);
}

// round 3
// speedup vs baseline: 3.7484x; 1.2947x over previous
#include <cuda_runtime.h>

#define TPB   256
#define LTPB  512
#define SLC   4
#define G     16
#define NCELL (G*G)
#define BPB   8
#define MAXB  128
#define MAXP  32768
#define MAXO  32
#define TIECAP 1024

typedef unsigned long long ull;

// ---------------- per-call zeroed scratch (single memset) -------------------
struct Zeroed {
    ull      best_prior[MAXB * MAXO];
    double   accB[MAXB][3];
    int      numpos[MAXB];
    int      tiecnt[MAXB];
    unsigned ccnt[NCELL];
    unsigned cfill[NCELL];
};
__device__ Zeroed gz;

// ---------------- other scratch ----------------------------------------------
__device__ unsigned char              g_tim     [(size_t)MAXB * MAXP]; // memset/call
__device__ __align__(16) float        g_loss_cpp[(size_t)MAXB * MAXP];
__device__ unsigned int               g_hist    [(size_t)MAXB * SLC * 2048];
__device__ int                        g_cellid  [MAXP];
__device__ int                        g_cstart  [NCELL + 1];
__device__ int                        g_plist   [MAXP];
__device__ float4                     g_psorted [MAXP];   // point-form boxes
__device__ int                        g_bin_a   [MAXB];
__device__ int                        g_bin_b   [MAXB];
__device__ int                        g_kcur    [MAXB];
__device__ unsigned int               g_T       [MAXB];
__device__ int                        g_needeq  [MAXB];
__device__ int                        g_tiebuf  [MAXB * TIECAP];

// ---------------- helpers ---------------------------------------------------
__device__ __forceinline__ float sl1(float d) {
    d = fabsf(d);
    return d < 1.0f ? 0.5f * d * d : d - 0.5f;
}
__device__ __forceinline__ float bce_term(float x, float tgt) {
    return fmaxf(x, 0.0f) - x * tgt + log1pf(expf(-fabsf(x)));
}
__device__ __forceinline__ float bce4v(float x0, float x1, float x2, float x3, int cls) {
    float s = 0.0f;
    s += bce_term(x0, (0 == cls) ? 0.925f : 0.025f);
    s += bce_term(x1, (1 == cls) ? 0.925f : 0.025f);
    s += bce_term(x2, (2 == cls) ? 0.925f : 0.025f);
    s += bce_term(x3, (3 == cls) ? 0.925f : 0.025f);
    return s;
}
template <int NT>
__device__ __forceinline__ float blocksumT(float v, float* sh) {
    int tid = threadIdx.x;
#pragma unroll
    for (int s = 16; s; s >>= 1) v += __shfl_down_sync(0xFFFFFFFFu, v, s);
    if ((tid & 31) == 0) sh[tid >> 5] = v;
    __syncthreads();
    const int NW = NT / 32;
    if (tid < NW) {
        v = sh[tid];
#pragma unroll
        for (int s = NW / 2; s; s >>= 1) v += __shfl_down_sync((1u << NW) - 1u, v, s);
    }
    __syncthreads();
    return v;
}

// ---------------- prior binning (priors are batch-invariant) ----------------
__global__ void kcount(const float4* __restrict__ priors4, int P) {
    int p = blockIdx.x * TPB + threadIdx.x;
    if (p >= P) return;
    float4 pr = priors4[p];
    int cx = min(G - 1, max(0, (int)(pr.x * G)));
    int cy = min(G - 1, max(0, (int)(pr.y * G)));
    int c = cy * G + cx;
    g_cellid[p] = c;
    atomicAdd(&gz.ccnt[c], 1u);
}

__global__ void kprefix() {
    if (threadIdx.x == 0) {
        int run = 0;
        for (int c = 0; c < NCELL; c++) {
            g_cstart[c] = run;
            gz.cfill[c] = (unsigned)run;
            run += (int)gz.ccnt[c];
        }
        g_cstart[NCELL] = run;
    }
}

__global__ void kscatter(const float4* __restrict__ priors4, int P) {
    int p = blockIdx.x * TPB + threadIdx.x;
    if (p >= P) return;
    int c = g_cellid[p];
    int pos = (int)atomicAdd(&gz.cfill[c], 1u);
    g_plist[pos] = p;
    float4 pr = priors4[p];
    float4 pf;
    pf.x = pr.x - pr.z * 0.5f; pf.y = pr.y - pr.w * 0.5f;
    pf.z = pr.x + pr.z * 0.5f; pf.w = pr.y + pr.w * 0.5f;
    g_psorted[pos] = pf;
}

// ---------------- kernel A: binned match ------------------------------------
// grid (NCELL, B/BPB), 128 threads. Candidate truths per cell via ballot.
__global__ void kmatch(const float* __restrict__ targets, int P, int O, int B) {
    int cell = blockIdx.x;
    int bbase = blockIdx.y * BPB;
    int start = g_cstart[cell], end = g_cstart[cell + 1];
    int tid = threadIdx.x;

    float inv = 1.0f / (float)G;
    const float M = 0.0501f;
    float rx0 = (cell % G) * inv - M, rx1 = (cell % G + 1) * inv + M;
    float ry0 = (cell / G) * inv - M, ry1 = (cell / G + 1) * inv + M;

    __shared__ float s_t[MAXO * 5];
    __shared__ ull   s_best[MAXO];
    __shared__ unsigned s_mask;

    for (int bb = 0; bb < BPB; bb++) {
        int b = bbase + bb;
        if (b >= B) break;
        if (tid < 32) {
            bool cand = false;
            if (tid < O) {
                const float* tr = targets + ((size_t)b * O + tid) * 6;
                float x0 = tr[0], y0 = tr[1], x1 = tr[2], y1 = tr[3];
                s_t[tid * 5 + 0] = x0; s_t[tid * 5 + 1] = y0;
                s_t[tid * 5 + 2] = x1; s_t[tid * 5 + 3] = y1;
                s_t[tid * 5 + 4] = (x1 - x0) * (y1 - y0);
                s_best[tid] = 0ull;
                cand = (x1 >= rx0) && (x0 <= rx1) && (y1 >= ry0) && (y0 <= ry1);
            }
            unsigned m = __ballot_sync(0xFFFFFFFFu, cand);
            if (tid == 0) s_mask = m;
        }
        __syncthreads();
        unsigned mask = s_mask;
        if (mask) {
            for (int i = start + tid; i < end; i += 128) {
                float4 pf = g_psorted[i];
                float aA = (pf.z - pf.x) * (pf.w - pf.y);
                int p = g_plist[i];
                float bv = 0.0f; int bo = 0;
                unsigned m = mask;
                while (m) {
                    int o = __ffs(m) - 1; m &= m - 1;
                    float ix = fminf(s_t[o * 5 + 2], pf.z) - fmaxf(s_t[o * 5 + 0], pf.x);
                    float iy = fminf(s_t[o * 5 + 3], pf.w) - fmaxf(s_t[o * 5 + 1], pf.y);
                    if (ix > 0.0f && iy > 0.0f) {
                        float inter = ix * iy;
                        float iou = inter / (s_t[o * 5 + 4] + aA - inter);
                        if (iou > bv) { bv = iou; bo = o; }
                        atomicMax(&s_best[o],
                            (((ull)__float_as_uint(iou)) << 32) | (unsigned)(~p));
                    }
                }
                if (bv >= 0.5f)
                    g_tim[(size_t)b * P + p] = (unsigned char)(0x80 | bo);
            }
        }
        __syncthreads();
        if (tid < O && s_best[tid] != 0ull)
            atomicMax(&gz.best_prior[b * O + tid], s_best[tid]);
        __syncthreads();
    }
}

// ---------------- kernel B: forced matches (ascending o, last wins) ---------
__global__ void kforce(int B, int P, int O) {
    int b = blockIdx.x * blockDim.x + threadIdx.x;
    if (b >= B) return;
    for (int o = 0; o < O; o++) {
        ull pk = gz.best_prior[b * O + o];
        unsigned p = ~(unsigned)pk;
        if (p < (unsigned)P)
            g_tim[(size_t)b * P + p] = (unsigned char)(0x80 | o);
    }
}

// ---------------- kernel C: per-prior losses + loss_cpp + hist level0 -------
__global__ void kloss(const float2* __restrict__ loc2, const float4* __restrict__ cnf4,
                      const float* __restrict__ reg, const float* __restrict__ targets,
                      const float4* __restrict__ priors4, int P, int O) {
    int b = blockIdx.y, slc = blockIdx.x;
    int cnt0 = (P + SLC - 1) / SLC;
    int base = slc * cnt0;
    int cnt = min(P - base, cnt0);

    __shared__ float s_t[MAXO * 6];
    __shared__ unsigned s_hist[2048];
    __shared__ float sh[LTPB / 32];

    int tid = threadIdx.x;
    for (int i = tid; i < O * 6; i += LTPB) s_t[i] = targets[(size_t)b * O * 6 + i];
    for (int i = tid; i < 2048; i += LTPB) s_hist[i] = 0;
    __syncthreads();

    float ll = 0, lc = 0, lr = 0, np = 0;
    for (int i = tid; i < cnt; i += LTPB) {
        int p = base + i;
        size_t idx = (size_t)b * P + p;
        unsigned char mv = g_tim[idx];
        float4 x = cnf4[idx];
        float lcpp;
        if (mv) {
            int ti = mv & 0x7F;
            int conf = (int)s_t[ti * 6 + 4];
            np += 1.0f;
            float4 pr = priors4[p];
            float mx = (s_t[ti * 6 + 0] + s_t[ti * 6 + 2]) * 0.5f;
            float my = (s_t[ti * 6 + 1] + s_t[ti * 6 + 3]) * 0.5f;
            float lt0 = (mx - pr.x) / (0.1f * pr.z);
            float lt1 = (my - pr.y) / (0.1f * pr.w);
            float2 lv = loc2[idx];
            ll += sl1(lv.x - lt0) + sl1(lv.y - lt1);
            lr += sl1(reg[idx] - s_t[ti * 6 + 5]);
            lc += bce4v(x.x, x.y, x.z, x.w, conf);
            lcpp = 0.0f;
        } else {
            float m = fmaxf(fmaxf(x.x, x.y), fmaxf(x.z, x.w));
            float s = expf(x.x - m) + expf(x.y - m) + expf(x.z - m) + expf(x.w - m);
            lcpp = m + logf(s) - x.x;
        }
        g_loss_cpp[idx] = lcpp;
        atomicAdd(&s_hist[__float_as_uint(lcpp) >> 21], 1u);
    }
    __syncthreads();

    unsigned* gh = &g_hist[((size_t)b * SLC + slc) * 2048];
    for (int i = tid; i < 2048; i += LTPB) gh[i] = s_hist[i];

    float tll = blocksumT<LTPB>(ll, sh);
    float tlc = blocksumT<LTPB>(lc, sh);
    float tlr = blocksumT<LTPB>(lr, sh);
    float tnp = blocksumT<LTPB>(np, sh);
    if (tid == 0) {
        atomicAdd(&gz.accB[b][0], (double)tll);
        atomicAdd(&gz.accB[b][1], (double)tlc);
        atomicAdd(&gz.accB[b][2], (double)tlr);
        atomicAdd(&gz.numpos[b], (int)tnp);
    }
}

// ---------------- radix level1/level2 histograms (float4) -------------------
__global__ void khist2(int P) {
    int b = blockIdx.y, slc = blockIdx.x;
    int cnt0 = (P + SLC - 1) / SLC;
    int base = slc * cnt0;
    int cnt = min(P - base, cnt0);
    __shared__ unsigned s_hist[2048];
    int tid = threadIdx.x;
    int ba = g_bin_a[b];
    for (int i = tid; i < 2048; i += LTPB) s_hist[i] = 0;
    __syncthreads();
    const float4* lc4 = (const float4*)&g_loss_cpp[(size_t)b * P + base];
    int n4 = cnt >> 2;
    for (int i = tid; i < n4; i += LTPB) {
        float4 v = lc4[i];
        unsigned b0 = __float_as_uint(v.x), b1 = __float_as_uint(v.y);
        unsigned b2 = __float_as_uint(v.z), b3 = __float_as_uint(v.w);
        if ((int)(b0 >> 21) == ba) atomicAdd(&s_hist[(b0 >> 10) & 0x7FF], 1u);
        if ((int)(b1 >> 21) == ba) atomicAdd(&s_hist[(b1 >> 10) & 0x7FF], 1u);
        if ((int)(b2 >> 21) == ba) atomicAdd(&s_hist[(b2 >> 10) & 0x7FF], 1u);
        if ((int)(b3 >> 21) == ba) atomicAdd(&s_hist[(b3 >> 10) & 0x7FF], 1u);
    }
    for (int i = (n4 << 2) + tid; i < cnt; i += LTPB) {
        unsigned bits = __float_as_uint(g_loss_cpp[(size_t)b * P + base + i]);
        if ((int)(bits >> 21) == ba) atomicAdd(&s_hist[(bits >> 10) & 0x7FF], 1u);
    }
    __syncthreads();
    unsigned* gh = &g_hist[((size_t)b * SLC + slc) * 2048];
    for (int i = tid; i < 2048; i += LTPB) gh[i] = s_hist[i];
}

__global__ void khist3(int P) {
    int b = blockIdx.y, slc = blockIdx.x;
    int cnt0 = (P + SLC - 1) / SLC;
    int base = slc * cnt0;
    int cnt = min(P - base, cnt0);
    __shared__ unsigned s_hist[1024];
    int tid = threadIdx.x;
    int top22 = (g_bin_a[b] << 11) | g_bin_b[b];
    for (int i = tid; i < 1024; i += LTPB) s_hist[i] = 0;
    __syncthreads();
    const float4* lc4 = (const float4*)&g_loss_cpp[(size_t)b * P + base];
    int n4 = cnt >> 2;
    for (int i = tid; i < n4; i += LTPB) {
        float4 v = lc4[i];
        unsigned b0 = __float_as_uint(v.x), b1 = __float_as_uint(v.y);
        unsigned b2 = __float_as_uint(v.z), b3 = __float_as_uint(v.w);
        if ((int)(b0 >> 10) == top22) atomicAdd(&s_hist[b0 & 0x3FF], 1u);
        if ((int)(b1 >> 10) == top22) atomicAdd(&s_hist[b1 & 0x3FF], 1u);
        if ((int)(b2 >> 10) == top22) atomicAdd(&s_hist[b2 & 0x3FF], 1u);
        if ((int)(b3 >> 10) == top22) atomicAdd(&s_hist[b3 & 0x3FF], 1u);
    }
    for (int i = (n4 << 2) + tid; i < cnt; i += LTPB) {
        unsigned bits = __float_as_uint(g_loss_cpp[(size_t)b * P + base + i]);
        if ((int)(bits >> 10) == top22) atomicAdd(&s_hist[bits & 0x3FF], 1u);
    }
    __syncthreads();
    unsigned* gh = &g_hist[((size_t)b * SLC + slc) * 2048];
    for (int i = tid; i < 1024; i += LTPB) gh[i] = s_hist[i];
}

// ---------------- scan: k-th largest bin from the top ------------------------
__global__ void kscan(int P, int level, int NB) {
    int b = blockIdx.x, t = threadIdx.x;
    __shared__ unsigned s_h[2048];
    __shared__ unsigned s_ce[256];
    int CH = NB / 256;
    const unsigned* gh = &g_hist[(size_t)b * SLC * 2048];
    for (int j = t; j < NB; j += 256) {
        unsigned s = 0;
#pragma unroll
        for (int s2 = 0; s2 < SLC; s2++) s += gh[s2 * 2048 + j];
        s_h[j] = s;
    }
    __syncthreads();
    unsigned cs = 0;
    for (int c = 0; c < CH; c++) cs += s_h[t * CH + c];
    s_ce[t] = cs;
    __syncthreads();
    if (t == 0) {
        unsigned run = 0;
        for (int u = 255; u >= 0; u--) { unsigned v = s_ce[u]; s_ce[u] = run; run += v; }
    }
    __syncthreads();

    int k;
    if (level == 0) { int npv = gz.numpos[b]; k = min(3 * npv, P - 1); }
    else            k = g_kcur[b];

    if (k > 0) {
        unsigned excl = s_ce[t];
        for (int j = (t + 1) * CH - 1; j >= t * CH; j--) {
            unsigned h = s_h[j];
            if (excl < (unsigned)k && excl + h >= (unsigned)k) {
                unsigned krem = (unsigned)k - excl;
                if (level == 0)      { g_bin_a[b] = j; g_kcur[b] = (int)krem; }
                else if (level == 1) { g_bin_b[b] = j; g_kcur[b] = (int)krem; }
                else {
                    g_T[b] = (((unsigned)g_bin_a[b]) << 21) |
                             (((unsigned)g_bin_b[b]) << 10) | (unsigned)j;
                    g_needeq[b] = (int)krem;
                }
                break;
            }
            excl += h;
        }
    } else if (t == 0) {
        if (level == 0)      { g_bin_a[b] = -1; g_kcur[b] = 0; }
        else if (level == 1) { g_bin_b[b] = -1; g_kcur[b] = 0; }
        else                 { g_T[b] = 0xFFFFFFFFu; g_needeq[b] = 0; }
    }
}

// ---------------- kernel D: hard-negative BCE (float4, 4/thread) ------------
__global__ void kneg(const float4* __restrict__ cnf4, int P) {
    int b = blockIdx.y;
    int i4 = blockIdx.x * TPB + threadIdx.x;
    __shared__ float sh[TPB / 32];
    float lc = 0.0f;
    int p0 = i4 * 4;
    unsigned T = g_T[b];
    if (p0 + 3 < P) {
        size_t idx = (size_t)b * P + p0;
        float4 v = *(const float4*)&g_loss_cpp[idx];
        unsigned bb[4] = { __float_as_uint(v.x), __float_as_uint(v.y),
                           __float_as_uint(v.z), __float_as_uint(v.w) };
#pragma unroll
        for (int j = 0; j < 4; j++) {
            if (bb[j] > T) {
                float4 x = cnf4[idx + j];
                lc += bce4v(x.x, x.y, x.z, x.w, 0);
            } else if (bb[j] == T && T != 0u) {
                int t = atomicAdd(&gz.tiecnt[b], 1);
                if (t < TIECAP) g_tiebuf[b * TIECAP + t] = p0 + j;
            }
        }
    } else {
        for (int p = p0; p < P; p++) {
            size_t idx = (size_t)b * P + p;
            unsigned bits = __float_as_uint(g_loss_cpp[idx]);
            if (bits > T) {
                float4 x = cnf4[idx];
                lc += bce4v(x.x, x.y, x.z, x.w, 0);
            } else if (bits == T && T != 0u) {
                int t = atomicAdd(&gz.tiecnt[b], 1);
                if (t < TIECAP) g_tiebuf[b * TIECAP + t] = p;
            }
        }
    }
    float tot = blocksumT<TPB>(lc, sh);
    if (threadIdx.x == 0 && tot != 0.0f)
        atomicAdd(&gz.accB[b][1], (double)tot);
}

// ---------------- kernel E: ties at threshold (smallest indices win) --------
__global__ void ktie(const float4* __restrict__ cnf4, int P) {
    int b = blockIdx.x;
    int t = min(gz.tiecnt[b], TIECAP);
    int need = g_needeq[b];
    __shared__ float sh[TPB / 32];
    float lc = 0.0f;
    for (int i = threadIdx.x; i < t; i += TPB) {
        int p = g_tiebuf[b * TIECAP + i];
        int rank = 0;
        for (int j = 0; j < t; j++) rank += (g_tiebuf[b * TIECAP + j] < p);
        if (rank < need) {
            float4 x = cnf4[(size_t)b * P + p];
            lc += bce4v(x.x, x.y, x.z, x.w, 0);
        }
    }
    float tot = blocksumT<TPB>(lc, sh);
    if (threadIdx.x == 0 && tot != 0.0f)
        atomicAdd(&gz.accB[b][1], (double)tot);
}

// ---------------- final reduce ----------------------------------------------
__global__ void kfinal(float* __restrict__ out, int B) {
    if (threadIdx.x == 0) {
        double N = 0, l0 = 0, l1 = 0, l2 = 0;
        for (int b = 0; b < B; b++) {
            N  += (double)gz.numpos[b];
            l0 += gz.accB[b][0];
            l1 += gz.accB[b][1];
            l2 += gz.accB[b][2];
        }
        out[0] = (float)(l0 / N);
        out[1] = (float)(l1 / N);
        out[2] = (float)(l2 / N);
    }
}

// ---------------- launch ------------------------------------------------------
extern "C" void kernel_launch(void* const* d_in, const int* in_sizes, int n_in,
                              void* d_out, int out_size) {
    const float* loc     = (const float*)d_in[0];
    const float* cnf     = (const float*)d_in[1];
    const float* reg     = (const float*)d_in[2];
    const float* targets = (const float*)d_in[3];
    const float* priors  = (const float*)d_in[4];

    int P = in_sizes[4] / 4;
    int B = in_sizes[0] / (2 * P);
    int O = in_sizes[3] / (6 * B);

    void *pz, *ptim;
    cudaGetSymbolAddress(&pz,   gz);
    cudaGetSymbolAddress(&ptim, g_tim);
    cudaMemsetAsync(pz,   0, sizeof(Zeroed), 0);
    cudaMemsetAsync(ptim, 0, (size_t)B * P, 0);

    dim3 gp((P + TPB - 1) / TPB);
    dim3 gm(NCELL, (B + BPB - 1) / BPB);
    dim3 gslice(SLC, B);
    dim3 gneg((P + 4 * TPB - 1) / (4 * TPB), B);

    kcount   <<<gp, TPB>>>((const float4*)priors, P);
    kprefix  <<<1, 32>>>();
    kscatter <<<gp, TPB>>>((const float4*)priors, P);
    kmatch   <<<gm, 128>>>(targets, P, O, B);
    kforce   <<<1, 128>>>(B, P, O);
    kloss    <<<gslice, LTPB>>>((const float2*)loc, (const float4*)cnf, reg,
                                targets, (const float4*)priors, P, O);
    kscan    <<<B, 256>>>(P, 0, 2048);
    khist2   <<<gslice, LTPB>>>(P);
    kscan    <<<B, 256>>>(P, 1, 2048);
    khist3   <<<gslice, LTPB>>>(P);
    kscan    <<<B, 256>>>(P, 2, 1024);
    kneg     <<<gneg, TPB>>>((const float4*)cnf, P);
    ktie     <<<B, TPB>>>((const float4*)cnf, P);
    kfinal   <<<1, 32>>>((float*)d_out, B);
}

// round 4
// speedup vs baseline: 5.1496x; 1.3738x over previous
#include <cuda_runtime.h>

#define TPB   256
#define LTPB  512
#define SLC   4
#define G     16
#define NCELL (G*G)
#define MAXB  128
#define MAXP  32768
#define MAXO  32
#define TIECAP 2048

typedef unsigned long long ull;

// ---------------- per-call zeroed scratch (single memset) -------------------
struct Zeroed {
    ull      best_prior[MAXB * MAXO];
    double   accB[MAXB][3];
    int      numpos[MAXB];
    int      tiecnt[MAXB];
    unsigned ccnt[NCELL];
    unsigned cfill[NCELL];
};
__device__ Zeroed gz;

// ---------------- other scratch ----------------------------------------------
__device__ unsigned char       g_tim     [(size_t)MAXB * MAXP]; // memset/call
__device__ __align__(16) float g_loss_cpp[(size_t)MAXB * MAXP];
__device__ unsigned int        g_hist    [(size_t)MAXB * SLC * 2048];
__device__ int                 g_cellid  [MAXP];
__device__ unsigned char       g_scell   [MAXP];   // cell of sorted prior
__device__ int                 g_cstart  [NCELL + 1];
__device__ int                 g_plist   [MAXP];
__device__ float4              g_psorted [MAXP];   // point-form boxes
__device__ unsigned            g_cmask   [MAXB * NCELL];
__device__ int                 g_bin_a   [MAXB];
__device__ int                 g_kcur    [MAXB];
__device__ unsigned int        g_T22     [MAXB];
__device__ int                 g_needeq  [MAXB];
__device__ ull                 g_tiebuf  [MAXB * TIECAP];

// ---------------- helpers ---------------------------------------------------
__device__ __forceinline__ float sl1(float d) {
    d = fabsf(d);
    return d < 1.0f ? 0.5f * d * d : d - 0.5f;
}
__device__ __forceinline__ float bce_term(float x, float tgt) {
    return fmaxf(x, 0.0f) - x * tgt + log1pf(expf(-fabsf(x)));
}
__device__ __forceinline__ float bce4v(float x0, float x1, float x2, float x3, int cls) {
    float s = 0.0f;
    s += bce_term(x0, (0 == cls) ? 0.925f : 0.025f);
    s += bce_term(x1, (1 == cls) ? 0.925f : 0.025f);
    s += bce_term(x2, (2 == cls) ? 0.925f : 0.025f);
    s += bce_term(x3, (3 == cls) ? 0.925f : 0.025f);
    return s;
}
template <int NT>
__device__ __forceinline__ float blocksumT(float v, float* sh) {
    int tid = threadIdx.x;
#pragma unroll
    for (int s = 16; s; s >>= 1) v += __shfl_down_sync(0xFFFFFFFFu, v, s);
    if ((tid & 31) == 0) sh[tid >> 5] = v;
    __syncthreads();
    const int NW = NT / 32;
    if (tid < NW) {
        v = sh[tid];
#pragma unroll
        for (int s = NW / 2; s; s >>= 1) v += __shfl_down_sync((1u << NW) - 1u, v, s);
    }
    __syncthreads();
    return v;
}

// ---------------- prior binning (priors are batch-invariant) ----------------
__global__ void kcount(const float4* __restrict__ priors4, int P) {
    int p = blockIdx.x * TPB + threadIdx.x;
    if (p >= P) return;
    float4 pr = priors4[p];
    int cx = min(G - 1, max(0, (int)(pr.x * G)));
    int cy = min(G - 1, max(0, (int)(pr.y * G)));
    int c = cy * G + cx;
    g_cellid[p] = c;
    atomicAdd(&gz.ccnt[c], 1u);
}

// 256-thread Hillis-Steele exclusive scan over 256 cell counts
__global__ void kprefix() {
    int t = threadIdx.x;
    __shared__ unsigned s[NCELL];
    unsigned mine = gz.ccnt[t];
    s[t] = mine;
    __syncthreads();
    for (int off = 1; off < NCELL; off <<= 1) {
        unsigned v = (t >= off) ? s[t - off] : 0u;
        __syncthreads();
        s[t] += v;
        __syncthreads();
    }
    unsigned excl = s[t] - mine;
    g_cstart[t] = (int)excl;
    gz.cfill[t] = excl;
    if (t == NCELL - 1) g_cstart[NCELL] = (int)s[t];
}

__global__ void kscatter(const float4* __restrict__ priors4, int P) {
    int p = blockIdx.x * TPB + threadIdx.x;
    if (p >= P) return;
    int c = g_cellid[p];
    int pos = (int)atomicAdd(&gz.cfill[c], 1u);
    g_plist[pos] = p;
    g_scell[pos] = (unsigned char)c;
    float4 pr = priors4[p];
    float4 pf;
    pf.x = pr.x - pr.z * 0.5f; pf.y = pr.y - pr.w * 0.5f;
    pf.z = pr.x + pr.z * 0.5f; pf.w = pr.y + pr.w * 0.5f;
    g_psorted[pos] = pf;
}

// ---------------- per-(batch,cell) candidate-truth masks --------------------
__global__ void kcmask(const float* __restrict__ targets, int O) {
    int b = blockIdx.x;
    int t = threadIdx.x;            // cell id, 256 threads
    __shared__ float s_t[MAXO * 4];
    if (t < O) {
        const float* tr = targets + ((size_t)b * O + t) * 6;
        s_t[t * 4 + 0] = tr[0]; s_t[t * 4 + 1] = tr[1];
        s_t[t * 4 + 2] = tr[2]; s_t[t * 4 + 3] = tr[3];
    }
    __syncthreads();
    const float inv = 1.0f / (float)G;
    const float M = 0.0501f;
    float rx0 = (t % G) * inv - M, rx1 = (t % G + 1) * inv + M;
    float ry0 = (t / G) * inv - M, ry1 = (t / G + 1) * inv + M;
    unsigned m = 0;
    for (int o = 0; o < O; o++) {
        if (s_t[o * 4 + 2] >= rx0 && s_t[o * 4 + 0] <= rx1 &&
            s_t[o * 4 + 3] >= ry0 && s_t[o * 4 + 1] <= ry1)
            m |= (1u << o);
    }
    g_cmask[b * NCELL + t] = m;
}

// ---------------- kernel A: binned match, one batch per block ---------------
__global__ void kmatch(const float* __restrict__ targets, int P, int O) {
    int b = blockIdx.y;
    int tid = threadIdx.x;
    __shared__ float s_t[MAXO * 5];
    __shared__ ull   s_best[MAXO];
    if (tid < O) {
        const float* tr = targets + ((size_t)b * O + tid) * 6;
        float x0 = tr[0], y0 = tr[1], x1 = tr[2], y1 = tr[3];
        s_t[tid * 5 + 0] = x0; s_t[tid * 5 + 1] = y0;
        s_t[tid * 5 + 2] = x1; s_t[tid * 5 + 3] = y1;
        s_t[tid * 5 + 4] = (x1 - x0) * (y1 - y0);
        s_best[tid] = 0ull;
    }
    __syncthreads();
    const unsigned* cmask = &g_cmask[b * NCELL];
    int base = blockIdx.x * 512;
#pragma unroll
    for (int rep = 0; rep < 2; rep++) {
        int i = base + rep * 256 + tid;
        if (i < P) {
            unsigned m = cmask[g_scell[i]];
            if (m) {
                float4 pf = g_psorted[i];
                float aA = (pf.z - pf.x) * (pf.w - pf.y);
                float bv = 0.0f; int bo = 0;
                int p = g_plist[i];
                do {
                    int o = __ffs(m) - 1; m &= m - 1;
                    float ix = fminf(s_t[o * 5 + 2], pf.z) - fmaxf(s_t[o * 5 + 0], pf.x);
                    float iy = fminf(s_t[o * 5 + 3], pf.w) - fmaxf(s_t[o * 5 + 1], pf.y);
                    if (ix > 0.0f && iy > 0.0f) {
                        float inter = ix * iy;
                        float iou = inter / (s_t[o * 5 + 4] + aA - inter);
                        if (iou > bv) { bv = iou; bo = o; }
                        atomicMax(&s_best[o],
                            (((ull)__float_as_uint(iou)) << 32) | (unsigned)(~p));
                    }
                } while (m);
                if (bv >= 0.5f)
                    g_tim[(size_t)b * P + p] = (unsigned char)(0x80 | bo);
            }
        }
    }
    __syncthreads();
    if (tid < O && s_best[tid] != 0ull)
        atomicMax(&gz.best_prior[b * O + tid], s_best[tid]);
}

// ---------------- kernel B: forced matches (ascending o, last wins) ---------
__global__ void kforce(int B, int P, int O) {
    int b = blockIdx.x * blockDim.x + threadIdx.x;
    if (b >= B) return;
    for (int o = 0; o < O; o++) {
        ull pk = gz.best_prior[b * O + o];
        unsigned p = ~(unsigned)pk;
        if (p < (unsigned)P)
            g_tim[(size_t)b * P + p] = (unsigned char)(0x80 | o);
    }
}

// ---------------- kernel C: per-prior losses + loss_cpp + hist level0 -------
__global__ void kloss(const float2* __restrict__ loc2, const float4* __restrict__ cnf4,
                      const float* __restrict__ reg, const float* __restrict__ targets,
                      const float4* __restrict__ priors4, int P, int O) {
    int b = blockIdx.y, slc = blockIdx.x;
    int cnt0 = (P + SLC - 1) / SLC;
    int base = slc * cnt0;
    int cnt = min(P - base, cnt0);

    __shared__ float s_t[MAXO * 6];
    __shared__ unsigned s_hist[2048];
    __shared__ float sh[LTPB / 32];

    int tid = threadIdx.x;
    for (int i = tid; i < O * 6; i += LTPB) s_t[i] = targets[(size_t)b * O * 6 + i];
    for (int i = tid; i < 2048; i += LTPB) s_hist[i] = 0;
    __syncthreads();

    float ll = 0, lc = 0, lr = 0, np = 0;
    for (int i = tid; i < cnt; i += LTPB) {
        int p = base + i;
        size_t idx = (size_t)b * P + p;
        unsigned char mv = g_tim[idx];
        float4 x = cnf4[idx];
        float lcpp;
        if (mv) {
            int ti = mv & 0x7F;
            int conf = (int)s_t[ti * 6 + 4];
            np += 1.0f;
            float4 pr = priors4[p];
            float mx = (s_t[ti * 6 + 0] + s_t[ti * 6 + 2]) * 0.5f;
            float my = (s_t[ti * 6 + 1] + s_t[ti * 6 + 3]) * 0.5f;
            float lt0 = (mx - pr.x) / (0.1f * pr.z);
            float lt1 = (my - pr.y) / (0.1f * pr.w);
            float2 lv = loc2[idx];
            ll += sl1(lv.x - lt0) + sl1(lv.y - lt1);
            lr += sl1(reg[idx] - s_t[ti * 6 + 5]);
            lc += bce4v(x.x, x.y, x.z, x.w, conf);
            lcpp = 0.0f;
        } else {
            float m = fmaxf(fmaxf(x.x, x.y), fmaxf(x.z, x.w));
            float s = expf(x.x - m) + expf(x.y - m) + expf(x.z - m) + expf(x.w - m);
            lcpp = m + logf(s) - x.x;
        }
        g_loss_cpp[idx] = lcpp;
        atomicAdd(&s_hist[__float_as_uint(lcpp) >> 21], 1u);
    }
    __syncthreads();

    unsigned* gh = &g_hist[((size_t)b * SLC + slc) * 2048];
    for (int i = tid; i < 2048; i += LTPB) gh[i] = s_hist[i];

    float tll = blocksumT<LTPB>(ll, sh);
    float tlc = blocksumT<LTPB>(lc, sh);
    float tlr = blocksumT<LTPB>(lr, sh);
    float tnp = blocksumT<LTPB>(np, sh);
    if (tid == 0) {
        atomicAdd(&gz.accB[b][0], (double)tll);
        atomicAdd(&gz.accB[b][1], (double)tlc);
        atomicAdd(&gz.accB[b][2], (double)tlr);
        atomicAdd(&gz.numpos[b], (int)tnp);
    }
}

// ---------------- radix level1 histogram (float4) ---------------------------
__global__ void khist2(int P) {
    int b = blockIdx.y, slc = blockIdx.x;
    int cnt0 = (P + SLC - 1) / SLC;
    int base = slc * cnt0;
    int cnt = min(P - base, cnt0);
    __shared__ unsigned s_hist[2048];
    int tid = threadIdx.x;
    int ba = g_bin_a[b];
    for (int i = tid; i < 2048; i += LTPB) s_hist[i] = 0;
    __syncthreads();
    const float4* lc4 = (const float4*)&g_loss_cpp[(size_t)b * P + base];
    int n4 = cnt >> 2;
    for (int i = tid; i < n4; i += LTPB) {
        float4 v = lc4[i];
        unsigned b0 = __float_as_uint(v.x), b1 = __float_as_uint(v.y);
        unsigned b2 = __float_as_uint(v.z), b3 = __float_as_uint(v.w);
        if ((int)(b0 >> 21) == ba) atomicAdd(&s_hist[(b0 >> 10) & 0x7FF], 1u);
        if ((int)(b1 >> 21) == ba) atomicAdd(&s_hist[(b1 >> 10) & 0x7FF], 1u);
        if ((int)(b2 >> 21) == ba) atomicAdd(&s_hist[(b2 >> 10) & 0x7FF], 1u);
        if ((int)(b3 >> 21) == ba) atomicAdd(&s_hist[(b3 >> 10) & 0x7FF], 1u);
    }
    for (int i = (n4 << 2) + tid; i < cnt; i += LTPB) {
        unsigned bits = __float_as_uint(g_loss_cpp[(size_t)b * P + base + i]);
        if ((int)(bits >> 21) == ba) atomicAdd(&s_hist[(bits >> 10) & 0x7FF], 1u);
    }
    __syncthreads();
    unsigned* gh = &g_hist[((size_t)b * SLC + slc) * 2048];
    for (int i = tid; i < 2048; i += LTPB) gh[i] = s_hist[i];
}

// ---------------- scan: k-th largest bin from the top (levels 0,1) ----------
__global__ void kscan(int P, int level) {
    int b = blockIdx.x, t = threadIdx.x;
    __shared__ unsigned s_h[2048];
    __shared__ unsigned s_ce[256];
    const int CH = 8;
    const unsigned* gh = &g_hist[(size_t)b * SLC * 2048];
    for (int j = t; j < 2048; j += 256) {
        unsigned s = 0;
#pragma unroll
        for (int s2 = 0; s2 < SLC; s2++) s += gh[s2 * 2048 + j];
        s_h[j] = s;
    }
    __syncthreads();
    unsigned cs = 0;
#pragma unroll
    for (int c = 0; c < CH; c++) cs += s_h[t * CH + c];
    s_ce[t] = cs;
    __syncthreads();
    if (t == 0) {
        unsigned run = 0;
        for (int u = 255; u >= 0; u--) { unsigned v = s_ce[u]; s_ce[u] = run; run += v; }
    }
    __syncthreads();

    int k;
    if (level == 0) { int npv = gz.numpos[b]; k = min(3 * npv, P - 1); }
    else            k = g_kcur[b];

    if (k > 0) {
        unsigned excl = s_ce[t];
        for (int j = (t + 1) * CH - 1; j >= t * CH; j--) {
            unsigned h = s_h[j];
            if (excl < (unsigned)k && excl + h >= (unsigned)k) {
                unsigned krem = (unsigned)k - excl;
                if (level == 0) { g_bin_a[b] = j; g_kcur[b] = (int)krem; }
                else {
                    g_T22[b]    = (((unsigned)g_bin_a[b]) << 11) | (unsigned)j;
                    g_needeq[b] = (int)krem;
                }
                break;
            }
            excl += h;
        }
    } else if (t == 0) {
        if (level == 0) { g_bin_a[b] = -1; g_kcur[b] = 0; }
        else            { g_T22[b] = 0xFFFFFFFFu; g_needeq[b] = 0; }
    }
}

// ---------------- kernel D: hard-negative BCE (22-bit threshold) ------------
__global__ void kneg(const float4* __restrict__ cnf4, int P) {
    int b = blockIdx.y;
    int i4 = blockIdx.x * TPB + threadIdx.x;
    __shared__ float sh[TPB / 32];
    float lc = 0.0f;
    int p0 = i4 * 4;
    unsigned T = g_T22[b];
    if (p0 + 3 < P) {
        size_t idx = (size_t)b * P + p0;
        float4 v = *(const float4*)&g_loss_cpp[idx];
        unsigned bb[4] = { __float_as_uint(v.x), __float_as_uint(v.y),
                           __float_as_uint(v.z), __float_as_uint(v.w) };
#pragma unroll
        for (int j = 0; j < 4; j++) {
            unsigned key = bb[j] >> 10;
            if (key > T) {
                float4 x = cnf4[idx + j];
                lc += bce4v(x.x, x.y, x.z, x.w, 0);
            } else if (key == T) {
                int t = atomicAdd(&gz.tiecnt[b], 1);
                if (t < TIECAP)
                    g_tiebuf[b * TIECAP + t] =
                        (((ull)bb[j]) << 32) | (unsigned)(~(p0 + j));
            }
        }
    } else {
        for (int p = p0; p < P; p++) {
            size_t idx = (size_t)b * P + p;
            unsigned bits = __float_as_uint(g_loss_cpp[idx]);
            unsigned key = bits >> 10;
            if (key > T) {
                float4 x = cnf4[idx];
                lc += bce4v(x.x, x.y, x.z, x.w, 0);
            } else if (key == T) {
                int t = atomicAdd(&gz.tiecnt[b], 1);
                if (t < TIECAP)
                    g_tiebuf[b * TIECAP + t] = (((ull)bits) << 32) | (unsigned)(~p);
            }
        }
    }
    float tot = blocksumT<TPB>(lc, sh);
    if (threadIdx.x == 0 && tot != 0.0f)
        atomicAdd(&gz.accB[b][1], (double)tot);
}

// ---------------- kernel E: rank within threshold bin ------------------------
// key = (bits<<32)|~p : bigger = higher loss, then smaller index. top `need` win.
__global__ void ktie(const float4* __restrict__ cnf4, int P) {
    int b = blockIdx.x;
    int t = min(gz.tiecnt[b], TIECAP);
    int need = g_needeq[b];
    __shared__ float sh[TPB / 32];
    float lc = 0.0f;
    for (int i = threadIdx.x; i < t; i += TPB) {
        ull key = g_tiebuf[b * TIECAP + i];
        int rank = 0;
        for (int j = 0; j < t; j++) rank += (g_tiebuf[b * TIECAP + j] > key);
        if (rank < need) {
            unsigned p = ~(unsigned)key;
            float4 x = cnf4[(size_t)b * P + p];
            lc += bce4v(x.x, x.y, x.z, x.w, 0);
        }
    }
    float tot = blocksumT<TPB>(lc, sh);
    if (threadIdx.x == 0 && tot != 0.0f)
        atomicAdd(&gz.accB[b][1], (double)tot);
}

// ---------------- final reduce (parallel) ------------------------------------
__global__ void kfinal(float* __restrict__ out, int B) {
    int t = threadIdx.x;   // 128
    double n = 0, l0 = 0, l1 = 0, l2 = 0;
    if (t < B) {
        n  = (double)gz.numpos[t];
        l0 = gz.accB[t][0];
        l1 = gz.accB[t][1];
        l2 = gz.accB[t][2];
    }
    __shared__ double sd[4][4];
#pragma unroll
    for (int s = 16; s; s >>= 1) {
        n  += __shfl_down_sync(0xFFFFFFFFu, n,  s);
        l0 += __shfl_down_sync(0xFFFFFFFFu, l0, s);
        l1 += __shfl_down_sync(0xFFFFFFFFu, l1, s);
        l2 += __shfl_down_sync(0xFFFFFFFFu, l2, s);
    }
    if ((t & 31) == 0) {
        sd[t >> 5][0] = n; sd[t >> 5][1] = l0;
        sd[t >> 5][2] = l1; sd[t >> 5][3] = l2;
    }
    __syncthreads();
    if (t == 0) {
        n = 0; l0 = 0; l1 = 0; l2 = 0;
        for (int w = 0; w < 4; w++) {
            n += sd[w][0]; l0 += sd[w][1]; l1 += sd[w][2]; l2 += sd[w][3];
        }
        out[0] = (float)(l0 / n);
        out[1] = (float)(l1 / n);
        out[2] = (float)(l2 / n);
    }
}

// ---------------- launch ------------------------------------------------------
extern "C" void kernel_launch(void* const* d_in, const int* in_sizes, int n_in,
                              void* d_out, int out_size) {
    const float* loc     = (const float*)d_in[0];
    const float* cnf     = (const float*)d_in[1];
    const float* reg     = (const float*)d_in[2];
    const float* targets = (const float*)d_in[3];
    const float* priors  = (const float*)d_in[4];

    int P = in_sizes[4] / 4;
    int B = in_sizes[0] / (2 * P);
    int O = in_sizes[3] / (6 * B);

    void *pz, *ptim;
    cudaGetSymbolAddress(&pz,   gz);
    cudaGetSymbolAddress(&ptim, g_tim);
    cudaMemsetAsync(pz,   0, sizeof(Zeroed), 0);
    cudaMemsetAsync(ptim, 0, (size_t)B * P, 0);

    dim3 gp((P + TPB - 1) / TPB);
    dim3 gm((P + 511) / 512, B);
    dim3 gslice(SLC, B);
    dim3 gneg((P / 4 + TPB - 1) / TPB, B);

    kcount   <<<gp, TPB>>>((const float4*)priors, P);
    kprefix  <<<1, NCELL>>>();
    kscatter <<<gp, TPB>>>((const float4*)priors, P);
    kcmask   <<<B, NCELL>>>(targets, O);
    kmatch   <<<gm, 256>>>(targets, P, O);
    kforce   <<<1, 128>>>(B, P, O);
    kloss    <<<gslice, LTPB>>>((const float2*)loc, (const float4*)cnf, reg,
                                targets, (const float4*)priors, P, O);
    kscan    <<<B, 256>>>(P, 0);
    khist2   <<<gslice, LTPB>>>(P);
    kscan    <<<B, 256>>>(P, 1);
    kneg     <<<gneg, TPB>>>((const float4*)cnf, P);
    ktie     <<<B, TPB>>>((const float4*)cnf, P);
    kfinal   <<<1, 128>>>((float*)d_out, B);
}